// round 5
// baseline (speedup 1.0000x reference)
#include <cuda_runtime.h>
#include <cuda_fp16.h>

// Problem constants (fixed by the reference: B=4, N=1024, FMAP=64, HID=32)
#define BB 4
#define NN 1024
#define FM 64
#define HID 32
#define ROWS (BB * NN)        // 4096
#define I_CHUNK 32

// Scratch for the precomputed projections, packed as half2 (h pairs).
// 4096 rows x 16 half2 = 128 KB each. __device__ globals (allocation-free).
__device__ __align__(16) __half2 g_A[ROWS * 16];  // A' = X@W1a + b1
__device__ __align__(16) __half2 g_C[ROWS * 16];  // C  = X@W1b

// ---------------------------------------------------------------------------
// Stage 1: per-row projections. One warp per row, lane = h index.
// ---------------------------------------------------------------------------
__global__ __launch_bounds__(256) void prep_kernel(
    const float* __restrict__ X,    // [ROWS, 64]
    const float* __restrict__ W1,   // [128, 32]
    const float* __restrict__ b1)   // [32]
{
    __shared__ float sW1[2 * FM * HID];   // 16 KB
    __shared__ float sX[8][FM];
    __shared__ float sA[8][HID];
    __shared__ float sCc[8][HID];

    int tid = threadIdx.x;
    #pragma unroll
    for (int idx = tid; idx < 2 * FM * HID; idx += 256) sW1[idx] = W1[idx];

    int warp = tid >> 5;
    int lane = tid & 31;
    int row  = blockIdx.x * 8 + warp;

    sX[warp][lane]      = X[row * FM + lane];
    sX[warp][lane + 32] = X[row * FM + lane + 32];
    __syncthreads();

    float a = b1[lane];   // fold b1 into A'
    float c = 0.0f;
    #pragma unroll
    for (int k = 0; k < FM; k++) {
        float xk = sX[warp][k];
        a = fmaf(xk, sW1[k * HID + lane], a);
        c = fmaf(xk, sW1[(k + FM) * HID + lane], c);
    }
    sA[warp][lane]  = a;
    sCc[warp][lane] = c;
    __syncwarp();

    if (lane < 16) {
        g_A[row * 16 + lane] = __floats2half2_rn(sA[warp][2 * lane],  sA[warp][2 * lane + 1]);
        g_C[row * 16 + lane] = __floats2half2_rn(sCc[warp][2 * lane], sCc[warp][2 * lane + 1]);
    }
}

// ---------------------------------------------------------------------------
// Stage 2: pairwise tanh + dot + sigmoid.
// grid = (N/256 j-tiles, N/I_CHUNK i-tiles, B); block = 256 threads.
// Thread t owns j = jtile*256 + t and loops over I_CHUNK i's.
// ---------------------------------------------------------------------------
__device__ __forceinline__ __half2 tanh2_approx(__half2 x) {
    unsigned xi = *reinterpret_cast<unsigned*>(&x);
    unsigned ri;
    asm("tanh.approx.f16x2 %0, %1;" : "=r"(ri) : "r"(xi));
    return *reinterpret_cast<__half2*>(&ri);
}

__global__ __launch_bounds__(256) void pair_kernel(
    const float* __restrict__ W2,   // [32]
    const float* __restrict__ b2,   // [1]
    float* __restrict__ out)        // [B, N, N]
{
    __shared__ __align__(16) __half2 sC[I_CHUNK * 16];

    const int b  = blockIdx.z;
    const int j  = blockIdx.x * 256 + threadIdx.x;
    const int i0 = blockIdx.y * I_CHUNK;
    const int t  = threadIdx.x;

    // Load the C tile (I_CHUNK rows x 16 half2 = 2 KB) into smem, vectorized.
    if (t < (I_CHUNK * 16) / 4) {
        reinterpret_cast<float4*>(sC)[t] =
            reinterpret_cast<const float4*>(g_C + ((size_t)b * NN + i0) * 16)[t];
    }

    // Per-thread A' row (register-resident) while the smem load is in flight.
    float4 av[4];
    const float4* gA = reinterpret_cast<const float4*>(g_A + ((size_t)b * NN + j) * 16);
    #pragma unroll
    for (int q = 0; q < 4; q++) av[q] = gA[q];
    const __half2* Aj = reinterpret_cast<const __half2*>(av);

    // W2 packed as half2 (register-resident, L1-cached loads).
    __half2 w2h[16];
    #pragma unroll
    for (int k = 0; k < 16; k++) w2h[k] = __floats2half2_rn(W2[2 * k], W2[2 * k + 1]);
    const float bias2 = b2[0];

    __syncthreads();

    float* outp = out + (size_t)b * NN * NN + (size_t)i0 * NN + j;

    #pragma unroll 2
    for (int ii = 0; ii < I_CHUNK; ii++) {
        const float4* crow = reinterpret_cast<const float4*>(sC + ii * 16);

        __half2 acc0 = __float2half2_rn(0.0f);
        __half2 acc1 = acc0, acc2 = acc0, acc3 = acc0;

        #pragma unroll
        for (int q = 0; q < 4; q++) {
            float4 cv = crow[q];                       // broadcast LDS.128
            const __half2* cs = reinterpret_cast<const __half2*>(&cv);
            __half2 t0 = tanh2_approx(__hadd2(Aj[4 * q + 0], cs[0]));
            __half2 t1 = tanh2_approx(__hadd2(Aj[4 * q + 1], cs[1]));
            __half2 t2 = tanh2_approx(__hadd2(Aj[4 * q + 2], cs[2]));
            __half2 t3 = tanh2_approx(__hadd2(Aj[4 * q + 3], cs[3]));
            acc0 = __hfma2(t0, w2h[4 * q + 0], acc0);  // 4 split accumulators
            acc1 = __hfma2(t1, w2h[4 * q + 1], acc1);  // keep partial sums small
            acc2 = __hfma2(t2, w2h[4 * q + 2], acc2);
            acc3 = __hfma2(t3, w2h[4 * q + 3], acc3);
        }

        float2 f0 = __half22float2(acc0);
        float2 f1 = __half22float2(acc1);
        float2 f2 = __half22float2(acc2);
        float2 f3 = __half22float2(acc3);
        float logit = ((f0.x + f0.y) + (f1.x + f1.y))
                    + ((f2.x + f2.y) + (f3.x + f3.y)) + bias2;

        // sigmoid, relative-accurate even for tiny outputs: 1/(1+e^{-x})
        float e = __expf(-logit);                      // MUFU.EX2
        outp[(size_t)ii * NN] = __fdividef(1.0f, 1.0f + e);  // MUFU.RCP
    }
}

// ---------------------------------------------------------------------------
// Launch: two graph-capturable kernel launches, no allocations, no syncs.
// Inputs (metadata order): X, W1, b1, W2, b2. Output: float32 [4,1024,1024].
// ---------------------------------------------------------------------------
extern "C" void kernel_launch(void* const* d_in, const int* in_sizes, int n_in,
                              void* d_out, int out_size)
{
    const float* X  = (const float*)d_in[0];
    const float* W1 = (const float*)d_in[1];
    const float* b1 = (const float*)d_in[2];
    const float* W2 = (const float*)d_in[3];
    const float* b2 = (const float*)d_in[4];
    float* out = (float*)d_out;

    prep_kernel<<<ROWS / 8, 256>>>(X, W1, b1);

    dim3 grid(NN / 256, NN / I_CHUNK, BB);   // (4, 32, 4) = 512 blocks
    pair_kernel<<<grid, 256>>>(W2, b2, out);
}

// round 6
// speedup vs baseline: 1.0462x; 1.0462x over previous
#include <cuda_runtime.h>
#include <cuda_fp16.h>

// Problem constants (fixed by the reference: B=4, N=1024, FMAP=64, HID=32)
#define BB 4
#define NN 1024
#define FM 64
#define HID 32
#define ROWS (BB * NN)        // 4096
#define I_CHUNK 16

// Precomputed projections, packed as half2 (h pairs). 4096 rows x 16 half2.
__device__ __align__(16) __half2 g_A[ROWS * 16];  // A' = X@W1a + b1
__device__ __align__(16) __half2 g_C[ROWS * 16];  // C  = X@W1b

// ---------------------------------------------------------------------------
// Stage 1: per-row projections. 8 warps/block, 4 rows per warp (W1 smem load
// amortized 4x vs round-5). lane = h index.
// ---------------------------------------------------------------------------
__global__ __launch_bounds__(256) void prep_kernel(
    const float* __restrict__ X,    // [ROWS, 64]
    const float* __restrict__ W1,   // [128, 32]
    const float* __restrict__ b1)   // [32]
{
    __shared__ float sW1[2 * FM * HID];   // 16 KB
    __shared__ float sX[8][FM];

    const int tid = threadIdx.x;
    for (int idx = tid; idx < 2 * FM * HID; idx += 256) sW1[idx] = W1[idx];

    const int warp = tid >> 5;
    const int lane = tid & 31;
    const float bias = b1[lane];
    __syncthreads();

    const int row0 = blockIdx.x * 32 + warp * 4;
    __half* Ah = reinterpret_cast<__half*>(g_A);
    __half* Ch = reinterpret_cast<__half*>(g_C);

    #pragma unroll
    for (int r = 0; r < 4; r++) {
        const int row = row0 + r;
        sX[warp][lane]      = X[row * FM + lane];
        sX[warp][lane + 32] = X[row * FM + lane + 32];
        __syncwarp();

        float a = bias;   // fold b1 into A'
        float c = 0.0f;
        #pragma unroll
        for (int k = 0; k < FM; k++) {
            float xk = sX[warp][k];                  // smem broadcast
            a = fmaf(xk, sW1[k * HID + lane], a);
            c = fmaf(xk, sW1[(k + FM) * HID + lane], c);
        }
        Ah[row * HID + lane] = __float2half_rn(a);
        Ch[row * HID + lane] = __float2half_rn(c);
        __syncwarp();
    }
}

// ---------------------------------------------------------------------------
// Stage 2: pairwise tanh + dot + sigmoid.
// grid = (N/256 j-tiles, N/I_CHUNK i-tiles, B) = 1024 blocks; block = 256.
// Thread t owns j = jtile*256 + t, loops over I_CHUNK i's.
// ---------------------------------------------------------------------------
__device__ __forceinline__ __half2 tanh2_approx(__half2 x) {
    unsigned xi = *reinterpret_cast<unsigned*>(&x);
    unsigned ri;
    asm("tanh.approx.f16x2 %0, %1;" : "=r"(ri) : "r"(xi));
    return *reinterpret_cast<__half2*>(&ri);
}

__device__ __forceinline__ float tanhf_approx(float x) {
    float r;
    asm("tanh.approx.f32 %0, %1;" : "=f"(r) : "f"(x));
    return r;
}

__global__ __launch_bounds__(256, 4) void pair_kernel(
    const float* __restrict__ W2,   // [32]
    const float* __restrict__ b2,   // [1]
    float* __restrict__ out)        // [B, N, N]
{
    __shared__ __align__(16) __half2 sC[I_CHUNK * 16];

    const int b  = blockIdx.z;
    const int j  = blockIdx.x * 256 + threadIdx.x;
    const int i0 = blockIdx.y * I_CHUNK;
    const int t  = threadIdx.x;

    // C tile (I_CHUNK rows x 16 half2 = 1 KB) into smem, vectorized.
    if (t < (I_CHUNK * 16) / 4) {
        reinterpret_cast<float4*>(sC)[t] =
            reinterpret_cast<const float4*>(g_C + ((size_t)b * NN + i0) * 16)[t];
    }

    // Per-thread A' row (register-resident) while the smem load is in flight.
    float4 av[4];
    const float4* gA = reinterpret_cast<const float4*>(g_A + ((size_t)b * NN + j) * 16);
    #pragma unroll
    for (int q = 0; q < 4; q++) av[q] = gA[q];
    const __half2* Aj = reinterpret_cast<const __half2*>(av);

    // W2/2 packed as half2 (sigmoid via 0.5 + 0.5*tanh(logit/2) needs W2/2).
    __half2 w2h[16];
    #pragma unroll
    for (int k = 0; k < 16; k++)
        w2h[k] = __floats2half2_rn(0.5f * W2[2 * k], 0.5f * W2[2 * k + 1]);
    const float bias2 = 0.5f * b2[0];

    __syncthreads();

    float* outp = out + (size_t)b * NN * NN + (size_t)i0 * NN + j;

    #pragma unroll 2
    for (int ii = 0; ii < I_CHUNK; ii++) {
        const float4* crow = reinterpret_cast<const float4*>(sC + ii * 16);

        __half2 acc0 = __float2half2_rn(0.0f);
        __half2 acc1 = acc0, acc2 = acc0, acc3 = acc0;

        #pragma unroll
        for (int q = 0; q < 4; q++) {
            float4 cv = crow[q];                       // broadcast LDS.128
            const __half2* cs = reinterpret_cast<const __half2*>(&cv);
            __half2 t0 = tanh2_approx(__hadd2(Aj[4 * q + 0], cs[0]));
            __half2 t1 = tanh2_approx(__hadd2(Aj[4 * q + 1], cs[1]));
            __half2 t2 = tanh2_approx(__hadd2(Aj[4 * q + 2], cs[2]));
            __half2 t3 = tanh2_approx(__hadd2(Aj[4 * q + 3], cs[3]));
            acc0 = __hfma2(t0, w2h[4 * q + 0], acc0);  // 4 split accumulators
            acc1 = __hfma2(t1, w2h[4 * q + 1], acc1);
            acc2 = __hfma2(t2, w2h[4 * q + 2], acc2);
            acc3 = __hfma2(t3, w2h[4 * q + 3], acc3);
        }

        // Lean reduction: 2 HADD2, 2 converts, 3 FADD.
        __half2 s01 = __hadd2(acc0, acc1);
        __half2 s23 = __hadd2(acc2, acc3);
        float2 f0 = __half22float2(s01);
        float2 f1 = __half22float2(s23);
        float half_logit = ((f0.x + f0.y) + (f1.x + f1.y)) + bias2;

        // sigmoid(x) = 0.5 + 0.5 * tanh(x/2)  — single MUFU op
        outp[(size_t)ii * NN] = fmaf(0.5f, tanhf_approx(half_logit), 0.5f);
    }
}

// ---------------------------------------------------------------------------
// Launch: two graph-capturable kernel launches, no allocations, no syncs.
// Inputs (metadata order): X, W1, b1, W2, b2. Output: float32 [4,1024,1024].
// ---------------------------------------------------------------------------
extern "C" void kernel_launch(void* const* d_in, const int* in_sizes, int n_in,
                              void* d_out, int out_size)
{
    const float* X  = (const float*)d_in[0];
    const float* W1 = (const float*)d_in[1];
    const float* b1 = (const float*)d_in[2];
    const float* W2 = (const float*)d_in[3];
    const float* b2 = (const float*)d_in[4];
    float* out = (float*)d_out;

    prep_kernel<<<ROWS / 32, 256>>>(X, W1, b1);

    dim3 grid(NN / 256, NN / I_CHUNK, BB);   // (4, 64, 4) = 1024 blocks
    pair_kernel<<<grid, 256>>>(W2, b2, out);
}

// round 7
// speedup vs baseline: 1.0469x; 1.0007x over previous
#include <cuda_runtime.h>
#include <cuda_fp16.h>

// Problem constants (fixed by the reference: B=4, N=1024, FMAP=64, HID=32)
#define BB 4
#define NN 1024
#define FM 64
#define HID 32
#define ROWS (BB * NN)        // 4096
#define I_CHUNK 16

// Precomputed projections, packed as half2 (h pairs). 4096 rows x 16 half2.
__device__ __align__(16) __half2 g_A[ROWS * 16];  // A' = X@W1a + b1
__device__ __align__(16) __half2 g_C[ROWS * 16];  // C  = X@W1b

// ---------------------------------------------------------------------------
// Stage 1: per-row projections. 8 warps/block, 4 rows per warp. lane = h.
// ---------------------------------------------------------------------------
__global__ __launch_bounds__(256) void prep_kernel(
    const float* __restrict__ X,    // [ROWS, 64]
    const float* __restrict__ W1,   // [128, 32]
    const float* __restrict__ b1)   // [32]
{
    __shared__ float sW1[2 * FM * HID];   // 16 KB
    __shared__ float sX[8][FM];

    const int tid = threadIdx.x;
    for (int idx = tid; idx < 2 * FM * HID; idx += 256) sW1[idx] = W1[idx];

    const int warp = tid >> 5;
    const int lane = tid & 31;
    const float bias = b1[lane];
    __syncthreads();

    const int row0 = blockIdx.x * 32 + warp * 4;
    __half* Ah = reinterpret_cast<__half*>(g_A);
    __half* Ch = reinterpret_cast<__half*>(g_C);

    #pragma unroll
    for (int r = 0; r < 4; r++) {
        const int row = row0 + r;
        sX[warp][lane]      = X[row * FM + lane];
        sX[warp][lane + 32] = X[row * FM + lane + 32];
        __syncwarp();

        float a = bias;   // fold b1 into A'
        float c = 0.0f;
        #pragma unroll
        for (int k = 0; k < FM; k++) {
            float xk = sX[warp][k];                  // smem broadcast
            a = fmaf(xk, sW1[k * HID + lane], a);
            c = fmaf(xk, sW1[(k + FM) * HID + lane], c);
        }
        Ah[row * HID + lane] = __float2half_rn(a);
        Ch[row * HID + lane] = __float2half_rn(c);
        __syncwarp();
    }
}

// ---------------------------------------------------------------------------
// Stage 2: pairwise tanh + dot + sigmoid, 2-way i-ILP.
// grid = (N/256, N/I_CHUNK, B) = 1024 blocks; block = 256; thread owns one j.
// ---------------------------------------------------------------------------
__device__ __forceinline__ __half2 tanh2_approx(__half2 x) {
    unsigned xi = *reinterpret_cast<unsigned*>(&x);
    unsigned ri;
    asm("tanh.approx.f16x2 %0, %1;" : "=r"(ri) : "r"(xi));
    return *reinterpret_cast<__half2*>(&ri);
}

__device__ __forceinline__ float tanhf_approx(float x) {
    float r;
    asm("tanh.approx.f32 %0, %1;" : "=f"(r) : "f"(x));
    return r;
}

__global__ __launch_bounds__(256, 4) void pair_kernel(
    const float* __restrict__ W2,   // [32]
    const float* __restrict__ b2,   // [1]
    float* __restrict__ out)        // [B, N, N]
{
    __shared__ __align__(16) __half2 sC[I_CHUNK * 16];

    const int b  = blockIdx.z;
    const int j  = blockIdx.x * 256 + threadIdx.x;
    const int i0 = blockIdx.y * I_CHUNK;
    const int t  = threadIdx.x;

    // C tile (I_CHUNK rows x 16 half2 = 1 KB) into smem, vectorized.
    if (t < (I_CHUNK * 16) / 4) {
        reinterpret_cast<float4*>(sC)[t] =
            reinterpret_cast<const float4*>(g_C + ((size_t)b * NN + i0) * 16)[t];
    }

    // Per-thread A' row (register-resident) while the smem load is in flight.
    float4 av[4];
    const float4* gA = reinterpret_cast<const float4*>(g_A + ((size_t)b * NN + j) * 16);
    #pragma unroll
    for (int q = 0; q < 4; q++) av[q] = gA[q];
    const __half2* Aj = reinterpret_cast<const __half2*>(av);

    // W2/2 packed as half2 (sigmoid via 0.5 + 0.5*tanh(logit/2)).
    __half2 w2h[16];
    #pragma unroll
    for (int k = 0; k < 16; k++)
        w2h[k] = __floats2half2_rn(0.5f * W2[2 * k], 0.5f * W2[2 * k + 1]);
    // Bias folded into accumulator init (exact to one rounding).
    const __half2 binit = __halves2half2(__float2half_rn(0.5f * b2[0]),
                                         __ushort_as_half((unsigned short)0));
    const __half2 hzero = __float2half2_rn(0.0f);

    __syncthreads();

    float* outp = out + (size_t)b * NN * NN + (size_t)i0 * NN + j;

    #pragma unroll
    for (int ii = 0; ii < I_CHUNK; ii += 2) {
        const float4* crow0 = reinterpret_cast<const float4*>(sC + ii * 16);
        const float4* crow1 = reinterpret_cast<const float4*>(sC + (ii + 1) * 16);

        // Two independent accumulation chains (i and i+1) for ILP.
        __half2 a0 = binit, a1 = hzero, a2 = hzero, a3 = hzero;   // i
        __half2 b0 = binit, b1v = hzero, b2v = hzero, b3 = hzero; // i+1

        #pragma unroll
        for (int q = 0; q < 4; q++) {
            float4 cv0 = crow0[q];                      // broadcast LDS.128
            float4 cv1 = crow1[q];
            const __half2* c0 = reinterpret_cast<const __half2*>(&cv0);
            const __half2* c1 = reinterpret_cast<const __half2*>(&cv1);

            __half2 t00 = tanh2_approx(__hadd2(Aj[4 * q + 0], c0[0]));
            __half2 t10 = tanh2_approx(__hadd2(Aj[4 * q + 0], c1[0]));
            __half2 t01 = tanh2_approx(__hadd2(Aj[4 * q + 1], c0[1]));
            __half2 t11 = tanh2_approx(__hadd2(Aj[4 * q + 1], c1[1]));
            __half2 t02 = tanh2_approx(__hadd2(Aj[4 * q + 2], c0[2]));
            __half2 t12 = tanh2_approx(__hadd2(Aj[4 * q + 2], c1[2]));
            __half2 t03 = tanh2_approx(__hadd2(Aj[4 * q + 3], c0[3]));
            __half2 t13 = tanh2_approx(__hadd2(Aj[4 * q + 3], c1[3]));

            a0  = __hfma2(t00, w2h[4 * q + 0], a0);
            b0  = __hfma2(t10, w2h[4 * q + 0], b0);
            a1  = __hfma2(t01, w2h[4 * q + 1], a1);
            b1v = __hfma2(t11, w2h[4 * q + 1], b1v);
            a2  = __hfma2(t02, w2h[4 * q + 2], a2);
            b2v = __hfma2(t12, w2h[4 * q + 2], b2v);
            a3  = __hfma2(t03, w2h[4 * q + 3], a3);
            b3  = __hfma2(t13, w2h[4 * q + 3], b3);
        }

        // Lean epilogue: 3 HADD2 + 1 HADD + 1 cvt + MUFU + FFMA + STG per i.
        __half2 sa = __hadd2(__hadd2(a0, a1), __hadd2(a2, a3));
        __half2 sb = __hadd2(__hadd2(b0, b1v), __hadd2(b2v, b3));
        float hla = __half2float(__hadd(__low2half(sa), __high2half(sa)));
        float hlb = __half2float(__hadd(__low2half(sb), __high2half(sb)));

        outp[(size_t)ii * NN]       = fmaf(0.5f, tanhf_approx(hla), 0.5f);
        outp[(size_t)(ii + 1) * NN] = fmaf(0.5f, tanhf_approx(hlb), 0.5f);
    }
}

// ---------------------------------------------------------------------------
// Launch: two graph-capturable kernel launches, no allocations, no syncs.
// Inputs (metadata order): X, W1, b1, W2, b2. Output: float32 [4,1024,1024].
// ---------------------------------------------------------------------------
extern "C" void kernel_launch(void* const* d_in, const int* in_sizes, int n_in,
                              void* d_out, int out_size)
{
    const float* X  = (const float*)d_in[0];
    const float* W1 = (const float*)d_in[1];
    const float* b1 = (const float*)d_in[2];
    const float* W2 = (const float*)d_in[3];
    const float* b2 = (const float*)d_in[4];
    float* out = (float*)d_out;

    prep_kernel<<<ROWS / 32, 256>>>(X, W1, b1);

    dim3 grid(NN / 256, NN / I_CHUNK, BB);   // (4, 64, 4) = 1024 blocks
    pair_kernel<<<grid, 256>>>(W2, b2, out);
}